// round 1
// baseline (speedup 1.0000x reference)
#include <cuda_runtime.h>
#include <cstdint>

#define ROW_LEN 2048
#define NTHREADS 256
#define VPT 8       // values per thread
#define K_TOP 64

// Monotone bijection: float -> uint32 such that float order == uint order.
__device__ __forceinline__ uint32_t f2u(float f) {
    uint32_t u = __float_as_uint(f);
    return (u & 0x80000000u) ? ~u : (u | 0x80000000u);
}
__device__ __forceinline__ float u2f(uint32_t u) {
    u = (u & 0x80000000u) ? (u & 0x7FFFFFFFu) : ~u;
    return __uint_as_float(u);
}

__global__ __launch_bounds__(NTHREADS)
void topk_softmax_kernel(const float* __restrict__ in, float* __restrict__ out) {
    const int row = blockIdx.x;
    const int tid = threadIdx.x;
    const float4* rp4 = reinterpret_cast<const float4*>(in + (size_t)row * ROW_LEN);
    float4*       op4 = reinterpret_cast<float4*>(out + (size_t)row * ROW_LEN);

    __shared__ int      hist[256];
    __shared__ float    s_red[8];
    __shared__ int      s_k;
    __shared__ uint32_t s_pref;
    __shared__ float    s_max, s_sum;

    // ---- 1. Load row into registers (2x float4 per thread, coalesced) ----
    float4 a = rp4[tid];
    float4 b = rp4[tid + NTHREADS];
    float v[VPT];
    v[0] = a.x; v[1] = a.y; v[2] = a.z; v[3] = a.w;
    v[4] = b.x; v[5] = b.y; v[6] = b.z; v[7] = b.w;

    // ---- 2. Row max (softmax stabilizer) ----
    float m = v[0];
    #pragma unroll
    for (int i = 1; i < VPT; i++) m = fmaxf(m, v[i]);
    #pragma unroll
    for (int o = 16; o; o >>= 1) m = fmaxf(m, __shfl_xor_sync(0xffffffffu, m, o));
    if ((tid & 31) == 0) s_red[tid >> 5] = m;
    if (tid == 0) { s_k = K_TOP; s_pref = 0u; }
    __syncthreads();
    if (tid < 8) {
        float mm = s_red[tid];
        #pragma unroll
        for (int o = 4; o; o >>= 1) mm = fmaxf(mm, __shfl_xor_sync(0xffu, mm, o));
        if (tid == 0) s_max = mm;
    }

    // ---- 3. Exact radix select of the 64th-largest value (4 x 8-bit passes) ----
    uint32_t key[VPT];
    #pragma unroll
    for (int i = 0; i < VPT; i++) key[i] = f2u(v[i]);

    #pragma unroll
    for (int pass = 0; pass < 4; pass++) {
        const int shift = 24 - pass * 8;
        // fixed-high-bits mask for this pass (0 for pass 0)
        const uint32_t pmask = (pass == 0) ? 0u : (0xFFFFFFFFu << (shift + 8));

        hist[tid] = 0;
        __syncthreads();                      // also publishes prior pass's s_pref/s_k
        const uint32_t pref = s_pref;
        const int      kcur = s_k;

        #pragma unroll
        for (int i = 0; i < VPT; i++) {
            if ((key[i] & pmask) == (pref & pmask))
                atomicAdd(&hist[(key[i] >> shift) & 0xFF], 1);
        }
        __syncthreads();

        // suffix sum: hist[t] = count of candidates with byte >= t
        #pragma unroll
        for (int o = 1; o < 256; o <<= 1) {
            int val = hist[tid];
            int add = (tid + o < 256) ? hist[tid + o] : 0;
            __syncthreads();
            hist[tid] = val + add;
            __syncthreads();
        }

        const int S  = hist[tid];
        const int Sn = (tid < 255) ? hist[tid + 1] : 0;
        __syncthreads();                      // all reads done before unique writer fires
        if (S >= kcur && Sn < kcur) {
            s_pref = pref | ((uint32_t)tid << shift);
            s_k    = kcur - Sn;
        }
        __syncthreads();
    }

    const float vk   = u2f(s_pref);           // bit-exact 64th-largest value
    const float rmax = s_max;

    // ---- 4. Masked exp + sum ----
    float sum = 0.0f;
    #pragma unroll
    for (int i = 0; i < VPT; i++) {
        float e = (v[i] >= vk) ? __expf(v[i] - rmax) : 0.0f;
        v[i] = e;
        sum += e;
    }
    #pragma unroll
    for (int o = 16; o; o >>= 1) sum += __shfl_xor_sync(0xffffffffu, sum, o);
    if ((tid & 31) == 0) s_red[tid >> 5] = sum;
    __syncthreads();
    if (tid < 8) {
        float ss = s_red[tid];
        #pragma unroll
        for (int o = 4; o; o >>= 1) ss += __shfl_xor_sync(0xffu, ss, o);
        if (tid == 0) s_sum = ss;
    }
    __syncthreads();

    const float inv = __fdividef(1.0f, s_sum);

    // ---- 5. Store (coalesced float4) ----
    float4 o1 = make_float4(v[0] * inv, v[1] * inv, v[2] * inv, v[3] * inv);
    float4 o2 = make_float4(v[4] * inv, v[5] * inv, v[6] * inv, v[7] * inv);
    op4[tid]            = o1;
    op4[tid + NTHREADS] = o2;
}

extern "C" void kernel_launch(void* const* d_in, const int* in_sizes, int n_in,
                              void* d_out, int out_size) {
    const float* in = (const float*)d_in[0];
    float* out = (float*)d_out;
    const int nrows = in_sizes[0] / ROW_LEN;   // 2*16*2048 = 65536
    topk_softmax_kernel<<<nrows, NTHREADS>>>(in, out);
}